// round 1
// baseline (speedup 1.0000x reference)
#include <cuda_runtime.h>
#include <cstdint>

// ---------------------------------------------------------------------------
// ProposalCaffe: 64x64 feature map, 9 anchors, stride 16, img 1024x1024.
// Pipeline: decode -> bitonic sort (65536 keys) -> gather top6000 -> NMS mask
//           -> chunked greedy scan -> write 300 boxes / 1024.
// ---------------------------------------------------------------------------

#define H 64
#define W 64
#define A 9
#define NPROP (H * W * A)        // 36864
#define NSORT 65536
#define PRE_NMS 6000
#define POST_NMS 300
#define MASK_W 94                // ceil(6000/64)

__device__ float4 g_props[NPROP];
__device__ unsigned long long g_keys[NSORT];
__device__ float4 g_top[PRE_NMS];
__device__ unsigned long long g_finite[MASK_W];
__device__ unsigned long long g_mask[(size_t)PRE_NMS * MASK_W];  // 4.5 MB

// Anchor table (exact integers; numpy banker's rounding applied)
__constant__ float c_anchors[A * 4] = {
    // r=0.5
    -84.f,  -40.f,  99.f,  55.f,
   -176.f,  -88.f, 191.f, 103.f,
   -360.f, -184.f, 375.f, 199.f,
    // r=1.0
    -56.f,  -56.f,  71.f,  71.f,
   -120.f, -120.f, 135.f, 135.f,
   -248.f, -248.f, 263.f, 263.f,
    // r=2.0
    -36.f,  -80.f,  51.f,  95.f,
    -80.f, -168.f,  95.f, 183.f,
   -168.f, -344.f, 183.f, 359.f,
};

// ---------------------------------------------------------------------------
// Kernel 1: decode proposals, build sort keys, pad tail keys.
// key = (~orderable(score) << 32) | index  -> ascending sort == top_k order
// ---------------------------------------------------------------------------
__global__ void k_props(const float* __restrict__ scores,
                        const float* __restrict__ deltas) {
    int tid = blockIdx.x * blockDim.x + threadIdx.x;
    if (tid >= NSORT) return;
    if (tid >= NPROP) { g_keys[tid] = ~0ULL; return; }

    int a = tid % A;
    int pix = tid / A;
    int x = pix % W;
    int y = pix / W;

    float s = scores[pix * (2 * A) + A + a];
    const float* d = deltas + pix * (4 * A) + a * 4;
    float dx = d[0], dy = d[1], dw = d[2], dh = d[3];

    float sx = (float)(x * 16);
    float sy = (float)(y * 16);
    float ax1 = c_anchors[a * 4 + 0] + sx;
    float ay1 = c_anchors[a * 4 + 1] + sy;
    float ax2 = c_anchors[a * 4 + 2] + sx;
    float ay2 = c_anchors[a * 4 + 3] + sy;

    float aw = ax2 - ax1 + 1.0f;
    float ah = ay2 - ay1 + 1.0f;
    float acx = ax1 + 0.5f * aw;
    float acy = ay1 + 0.5f * ah;

    float pcx = dx * aw + acx;
    float pcy = dy * ah + acy;
    float pw = expf(dw) * aw;
    float ph = expf(dh) * ah;

    float x1 = fminf(fmaxf(pcx - 0.5f * pw, 0.0f), 1023.0f);
    float y1 = fminf(fmaxf(pcy - 0.5f * ph, 0.0f), 1023.0f);
    float x2 = fminf(fmaxf(pcx + 0.5f * pw, 0.0f), 1023.0f);
    float y2 = fminf(fmaxf(pcy + 0.5f * ph, 0.0f), 1023.0f);

    g_props[tid] = make_float4(x1, y1, x2, y2);

    bool valid = ((x2 - x1 + 1.0f) >= 16.0f) && ((y2 - y1 + 1.0f) >= 16.0f);
    float ms = valid ? s : __int_as_float(0xff800000);  // -inf

    unsigned int bits = __float_as_uint(ms);
    unsigned int u = (bits & 0x80000000u) ? ~bits : (bits | 0x80000000u);
    unsigned int k = ~u;  // ascending k == descending score
    g_keys[tid] = ((unsigned long long)k << 32) | (unsigned int)tid;
}

// ---------------------------------------------------------------------------
// Bitonic sort on g_keys[65536] (ascending).
// ---------------------------------------------------------------------------
__global__ void k_sort_local() {  // full network k=2..2048 within 2048 chunks
    __shared__ unsigned long long s[2048];
    int base = blockIdx.x * 2048;
    s[threadIdx.x] = g_keys[base + threadIdx.x];
    s[threadIdx.x + 1024] = g_keys[base + threadIdx.x + 1024];
    __syncthreads();
    for (int k = 2; k <= 2048; k <<= 1) {
        for (int j = k >> 1; j > 0; j >>= 1) {
            int t = threadIdx.x;
            int i = 2 * t - (t & (j - 1));
            int l = i + j;
            bool up = (((base + i) & k) == 0);
            unsigned long long va = s[i], vb = s[l];
            if ((va > vb) == up) { s[i] = vb; s[l] = va; }
            __syncthreads();
        }
    }
    g_keys[base + threadIdx.x] = s[threadIdx.x];
    g_keys[base + threadIdx.x + 1024] = s[threadIdx.x + 1024];
}

__global__ void k_merge_global(int k, int j) {  // one (k,j) step, j >= 2048
    int t = blockIdx.x * blockDim.x + threadIdx.x;  // 32768 threads
    int i = 2 * t - (t & (j - 1));
    int l = i + j;
    bool up = ((i & k) == 0);
    unsigned long long va = g_keys[i], vb = g_keys[l];
    if ((va > vb) == up) { g_keys[i] = vb; g_keys[l] = va; }
}

__global__ void k_merge_shared(int k) {  // j = 1024..1 within 2048 chunks
    __shared__ unsigned long long s[2048];
    int base = blockIdx.x * 2048;
    s[threadIdx.x] = g_keys[base + threadIdx.x];
    s[threadIdx.x + 1024] = g_keys[base + threadIdx.x + 1024];
    __syncthreads();
    bool up = ((base & k) == 0);  // k >= 4096 -> uniform per block
    for (int j = 1024; j > 0; j >>= 1) {
        int t = threadIdx.x;
        int i = 2 * t - (t & (j - 1));
        int l = i + j;
        unsigned long long va = s[i], vb = s[l];
        if ((va > vb) == up) { s[i] = vb; s[l] = va; }
        __syncthreads();
    }
    g_keys[base + threadIdx.x] = s[threadIdx.x];
    g_keys[base + threadIdx.x + 1024] = s[threadIdx.x + 1024];
}

// ---------------------------------------------------------------------------
// Gather top-6000 boxes + per-chunk finite bitmask. grid=94, block=64.
// ---------------------------------------------------------------------------
__global__ void k_gather() {
    __shared__ unsigned int parts[2];
    int i = blockIdx.x * 64 + threadIdx.x;
    bool in = (i < PRE_NMS);
    unsigned long long key = in ? g_keys[i] : ~0ULL;
    if (in) {
        int idx = (int)(key & 0xFFFFFFFFu);
        g_top[i] = g_props[idx];
    }
    bool fin = in && ((key >> 32) <= 0x7FFFFFFFull);
    unsigned int m = __ballot_sync(0xffffffffu, fin);
    if ((threadIdx.x & 31) == 0) parts[threadIdx.x >> 5] = m;
    __syncthreads();
    if (threadIdx.x == 0)
        g_finite[blockIdx.x] = ((unsigned long long)parts[1] << 32) | parts[0];
}

// ---------------------------------------------------------------------------
// NMS suppression mask (upper triangle incl. diagonal block).
// grid (94,94), block 64. bit c of mask[i*94 + cb] : iou(i, cb*64+c) > 0.5
// Diagonal block sets bits only for col > row.
// ---------------------------------------------------------------------------
__global__ void k_mask() {
    int cb = blockIdx.x, rb = blockIdx.y;
    if (cb < rb) return;
    int row_n = min(PRE_NMS - rb * 64, 64);
    int col_n = min(PRE_NMS - cb * 64, 64);

    __shared__ float4 colb[64];
    if (threadIdx.x < col_n) colb[threadIdx.x] = g_top[cb * 64 + threadIdx.x];
    __syncthreads();

    if (threadIdx.x < row_n) {
        int i = rb * 64 + threadIdx.x;
        float4 b = g_top[i];
        float area_i = (b.z - b.x + 1.0f) * (b.w - b.y + 1.0f);
        unsigned long long bits = 0ULL;
        int start = (rb == cb) ? (threadIdx.x + 1) : 0;
        for (int c = start; c < col_n; c++) {
            float4 o = colb[c];
            float xx1 = fmaxf(b.x, o.x);
            float yy1 = fmaxf(b.y, o.y);
            float xx2 = fminf(b.z, o.z);
            float yy2 = fminf(b.w, o.w);
            float iw = fmaxf(xx2 - xx1 + 1.0f, 0.0f);
            float ih = fmaxf(yy2 - yy1 + 1.0f, 0.0f);
            float inter = iw * ih;
            float area_o = (o.z - o.x + 1.0f) * (o.w - o.y + 1.0f);
            float iou = inter / (area_i + area_o - inter);
            if (iou > 0.5f) bits |= (1ULL << c);
        }
        g_mask[(size_t)i * MASK_W + cb] = bits;
    }
}

// ---------------------------------------------------------------------------
// Chunked greedy scan, single warp. Each lane owns remv words lane, lane+32,
// lane+64. Intra-chunk suppression via diagonal word (shfl on kept bits only),
// cross-chunk ORs deferred to chunk end. Early exit at 300 picks.
// ---------------------------------------------------------------------------
__global__ void k_scan(float* __restrict__ out) {
    int lane = threadIdx.x;
    for (int t = lane; t < POST_NMS * 4; t += 32) out[t] = 0.0f;

    __shared__ int s_pick[POST_NMS];
    unsigned long long r0 = 0, r1 = 0, r2 = 0;
    int np = 0;
    const float inv = 1.0f / 1024.0f;

    for (int c = 0; c < MASK_W; c++) {
        unsigned long long rw = (c < 32) ? r0 : ((c < 64) ? r1 : r2);
        unsigned long long r = __shfl_sync(0xffffffffu, rw, c & 31);
        unsigned long long fw = g_finite[c];
        int nrows = min(PRE_NMS - c * 64, 64);

        unsigned long long d0 = (lane < nrows)
            ? g_mask[(size_t)(c * 64 + lane) * MASK_W + c] : 0ULL;
        unsigned long long d1 = (lane + 32 < nrows)
            ? g_mask[(size_t)(c * 64 + lane + 32) * MASK_W + c] : 0ULL;

        unsigned long long keptm = 0ULL;
        bool stop = false;
        for (int b = 0; b < nrows; b++) {
            if ((r >> b) & 1ULL) continue;
            keptm |= (1ULL << b);
            if ((fw >> b) & 1ULL) {
                if (lane == 0) s_pick[np] = c * 64 + b;
                np++;
                if (np == POST_NMS) { stop = true; break; }
            }
            unsigned long long dv = (b < 32) ? d0 : d1;
            dv = __shfl_sync(0xffffffffu, dv, b & 31);
            r |= dv;
        }
        if (stop) break;

        // Deferred OR of this chunk's kept rows into full remv.
        unsigned long long km = keptm;
        while (km) {
            int b = __ffsll(km) - 1;
            km &= km - 1;
            size_t row = (size_t)(c * 64 + b) * MASK_W;
            r0 |= g_mask[row + lane];
            if (lane + 32 < MASK_W) r1 |= g_mask[row + lane + 32];
            if (lane + 64 < MASK_W) r2 |= g_mask[row + lane + 64];
        }
    }

    __syncwarp();
    for (int p = lane; p < np; p += 32) {
        int i = s_pick[p];
        float4 b = g_top[i];
        out[p * 4 + 0] = b.x * inv;
        out[p * 4 + 1] = b.y * inv;
        out[p * 4 + 2] = b.z * inv;
        out[p * 4 + 3] = b.w * inv;
    }
}

// ---------------------------------------------------------------------------
extern "C" void kernel_launch(void* const* d_in, const int* in_sizes, int n_in,
                              void* d_out, int out_size) {
    const float* scores = (const float*)d_in[0];
    const float* deltas = (const float*)d_in[1];
    float* out = (float*)d_out;

    k_props<<<NSORT / 1024, 1024>>>(scores, deltas);
    k_sort_local<<<NSORT / 2048, 1024>>>();
    for (int k = 4096; k <= NSORT; k <<= 1) {
        for (int j = k >> 1; j >= 2048; j >>= 1) {
            k_merge_global<<<(NSORT / 2) / 512, 512>>>(k, j);
        }
        k_merge_shared<<<NSORT / 2048, 1024>>>(k);
    }
    k_gather<<<MASK_W, 64>>>();
    k_mask<<<dim3(MASK_W, MASK_W), 64>>>();
    k_scan<<<1, 32>>>(out);
}

// round 2
// speedup vs baseline: 1.0673x; 1.0673x over previous
#include <cuda_runtime.h>
#include <cstdint>

// ---------------------------------------------------------------------------
// ProposalCaffe: 64x64 feature map, 9 anchors, stride 16, img 1024x1024.
// Pipeline: decode(+hist) -> radix-select cut -> compact (~6.1k) ->
//           bitonic sort 8192 -> gather top6000 -> NMS mask -> greedy scan.
// ---------------------------------------------------------------------------

#define H 64
#define W 64
#define A 9
#define NPROP (H * W * A)        // 36864
#define NCAND 8192
#define PRE_NMS 6000
#define POST_NMS 300
#define MASK_W 94                // ceil(6000/64)

typedef unsigned long long ull;

__device__ float4 g_props[NPROP];
__device__ ull    g_keys[NPROP];
__device__ ull    g_sort[NCAND];
__device__ float4 g_top[PRE_NMS];
__device__ ull    g_finite[MASK_W];
__device__ ull    g_mask[(size_t)PRE_NMS * MASK_W];  // 4.5 MB
__device__ int    g_hist1[256];
__device__ int    g_cnt;
__device__ int    g_cut16;

// Anchor table (exact integers; numpy banker's rounding applied)
__constant__ float c_anchors[A * 4] = {
    -84.f,  -40.f,  99.f,  55.f,
   -176.f,  -88.f, 191.f, 103.f,
   -360.f, -184.f, 375.f, 199.f,
    -56.f,  -56.f,  71.f,  71.f,
   -120.f, -120.f, 135.f, 135.f,
   -248.f, -248.f, 263.f, 263.f,
    -36.f,  -80.f,  51.f,  95.f,
    -80.f, -168.f,  95.f, 183.f,
   -168.f, -344.f, 183.f, 359.f,
};

// ---------------------------------------------------------------------------
// Reset state for this invocation (device globals persist across graph replays)
// ---------------------------------------------------------------------------
__global__ void k_zero() {
    int tid = blockIdx.x * blockDim.x + threadIdx.x;
    if (tid < NCAND) g_sort[tid] = ~0ULL;
    else if (tid < NCAND + 256) g_hist1[tid - NCAND] = 0;
    else if (tid == NCAND + 256) g_cnt = 0;
}

// ---------------------------------------------------------------------------
// Decode proposals, build sort keys, histogram top 8 key bits.
// key = (~orderable(score) << 32) | index  -> ascending sort == top_k order
// ---------------------------------------------------------------------------
__global__ void k_props(const float* __restrict__ scores,
                        const float* __restrict__ deltas) {
    int tid = blockIdx.x * blockDim.x + threadIdx.x;
    if (tid >= NPROP) return;

    int a = tid % A;
    int pix = tid / A;
    int x = pix % W;
    int y = pix / W;

    float s = scores[pix * (2 * A) + A + a];
    const float* d = deltas + pix * (4 * A) + a * 4;
    float dx = d[0], dy = d[1], dw = d[2], dh = d[3];

    float sx = (float)(x * 16);
    float sy = (float)(y * 16);
    float ax1 = c_anchors[a * 4 + 0] + sx;
    float ay1 = c_anchors[a * 4 + 1] + sy;
    float ax2 = c_anchors[a * 4 + 2] + sx;
    float ay2 = c_anchors[a * 4 + 3] + sy;

    float aw = ax2 - ax1 + 1.0f;
    float ah = ay2 - ay1 + 1.0f;
    float acx = ax1 + 0.5f * aw;
    float acy = ay1 + 0.5f * ah;

    float pcx = dx * aw + acx;
    float pcy = dy * ah + acy;
    float pw = expf(dw) * aw;
    float ph = expf(dh) * ah;

    float x1 = fminf(fmaxf(pcx - 0.5f * pw, 0.0f), 1023.0f);
    float y1 = fminf(fmaxf(pcy - 0.5f * ph, 0.0f), 1023.0f);
    float x2 = fminf(fmaxf(pcx + 0.5f * pw, 0.0f), 1023.0f);
    float y2 = fminf(fmaxf(pcy + 0.5f * ph, 0.0f), 1023.0f);

    g_props[tid] = make_float4(x1, y1, x2, y2);

    bool valid = ((x2 - x1 + 1.0f) >= 16.0f) && ((y2 - y1 + 1.0f) >= 16.0f);
    float ms = valid ? s : __int_as_float(0xff800000);  // -inf

    unsigned int bits = __float_as_uint(ms);
    unsigned int u = (bits & 0x80000000u) ? ~bits : (bits | 0x80000000u);
    unsigned int k = ~u;  // ascending k == descending score
    g_keys[tid] = ((ull)k << 32) | (unsigned int)tid;
    atomicAdd(&g_hist1[k >> 24], 1);
}

// ---------------------------------------------------------------------------
// Find 16-bit key-prefix cut such that #(prefix16 <= cut) >= 6000,
// excess bounded by one sub-bin. Single block.
// ---------------------------------------------------------------------------
__global__ void k_select() {
    __shared__ int sh2[256];
    __shared__ int s_B, s_lt;
    int tid = threadIdx.x;
    if (tid < 256) sh2[tid] = 0;
    if (tid == 0) {
        int cum = 0, B = 255, lt = 0;
        for (int b = 0; b < 256; b++) {
            int c = g_hist1[b];
            if (cum + c >= PRE_NMS) { B = b; lt = cum; break; }
            cum += c;
        }
        s_B = B; s_lt = lt;
    }
    __syncthreads();
    int B = s_B;
    for (int i = tid; i < NPROP; i += 1024) {
        unsigned int k = (unsigned int)(g_keys[i] >> 32);
        if ((int)(k >> 24) == B) atomicAdd(&sh2[(k >> 16) & 255], 1);
    }
    __syncthreads();
    if (tid == 0) {
        int cum = s_lt, B2 = 255;
        for (int b = 0; b < 256; b++) {
            cum += sh2[b];
            if (cum >= PRE_NMS) { B2 = b; break; }
        }
        g_cut16 = (B << 8) | B2;
    }
}

// ---------------------------------------------------------------------------
// Compact candidate keys (prefix16 <= cut) into g_sort (padded with ~0).
// ---------------------------------------------------------------------------
__global__ void k_compact() {
    int tid = blockIdx.x * blockDim.x + threadIdx.x;
    if (tid >= NPROP) return;
    ull key = g_keys[tid];
    if ((int)(key >> 48) <= g_cut16) {
        int pos = atomicAdd(&g_cnt, 1);
        if (pos < NCAND) g_sort[pos] = key;
    }
}

// ---------------------------------------------------------------------------
// Bitonic sort of g_sort[8192] ascending.
// Stage 1: 4 blocks sort 2048-chunks (directions from global index).
// ---------------------------------------------------------------------------
__global__ void k_sort_local() {
    __shared__ ull s[2048];
    int base = blockIdx.x * 2048;
    s[threadIdx.x] = g_sort[base + threadIdx.x];
    s[threadIdx.x + 1024] = g_sort[base + threadIdx.x + 1024];
    __syncthreads();
    for (int k = 2; k <= 2048; k <<= 1) {
        for (int j = k >> 1; j > 0; j >>= 1) {
            int t = threadIdx.x;
            int i = 2 * t - (t & (j - 1));
            int l = i + j;
            bool up = (((base + i) & k) == 0);
            ull va = s[i], vb = s[l];
            if ((va > vb) == up) { s[i] = vb; s[l] = va; }
            __syncthreads();
        }
    }
    g_sort[base + threadIdx.x] = s[threadIdx.x];
    g_sort[base + threadIdx.x + 1024] = s[threadIdx.x + 1024];
}

// Stage 2: single block, 64KB dynamic smem, phases k=4096 and k=8192.
__global__ void k_sort_final() {
    extern __shared__ ull s[];
    int t = threadIdx.x;
    for (int i = t; i < NCAND; i += 1024) s[i] = g_sort[i];
    __syncthreads();
    for (int k = 4096; k <= 8192; k <<= 1) {
        for (int j = k >> 1; j > 0; j >>= 1) {
            for (int p = t; p < NCAND / 2; p += 1024) {
                int i = 2 * p - (p & (j - 1));
                int l = i + j;
                bool up = ((i & k) == 0);
                ull va = s[i], vb = s[l];
                if ((va > vb) == up) { s[i] = vb; s[l] = va; }
            }
            __syncthreads();
        }
    }
    for (int i = t; i < NCAND; i += 1024) g_sort[i] = s[i];
}

// ---------------------------------------------------------------------------
// Gather top-6000 boxes + per-chunk finite bitmask. grid=94, block=64.
// ---------------------------------------------------------------------------
__global__ void k_gather() {
    __shared__ unsigned int parts[2];
    int i = blockIdx.x * 64 + threadIdx.x;
    bool in = (i < PRE_NMS);
    ull key = in ? g_sort[i] : ~0ULL;
    if (in) {
        int idx = (int)(key & 0xFFFFFFFFu);
        g_top[i] = g_props[idx];
    }
    bool fin = in && ((key >> 32) <= 0x7FFFFFFFull);
    unsigned int m = __ballot_sync(0xffffffffu, fin);
    if ((threadIdx.x & 31) == 0) parts[threadIdx.x >> 5] = m;
    __syncthreads();
    if (threadIdx.x == 0)
        g_finite[blockIdx.x] = ((ull)parts[1] << 32) | parts[0];
}

// ---------------------------------------------------------------------------
// NMS suppression mask (upper triangle incl. diagonal block).
// ---------------------------------------------------------------------------
__global__ void k_mask() {
    int cb = blockIdx.x, rb = blockIdx.y;
    if (cb < rb) return;
    int row_n = min(PRE_NMS - rb * 64, 64);
    int col_n = min(PRE_NMS - cb * 64, 64);

    __shared__ float4 colb[64];
    if (threadIdx.x < col_n) colb[threadIdx.x] = g_top[cb * 64 + threadIdx.x];
    __syncthreads();

    if (threadIdx.x < row_n) {
        int i = rb * 64 + threadIdx.x;
        float4 b = g_top[i];
        float area_i = (b.z - b.x + 1.0f) * (b.w - b.y + 1.0f);
        ull bits = 0ULL;
        int start = (rb == cb) ? (threadIdx.x + 1) : 0;
        for (int c = start; c < col_n; c++) {
            float4 o = colb[c];
            float xx1 = fmaxf(b.x, o.x);
            float yy1 = fmaxf(b.y, o.y);
            float xx2 = fminf(b.z, o.z);
            float yy2 = fminf(b.w, o.w);
            float iw = fmaxf(xx2 - xx1 + 1.0f, 0.0f);
            float ih = fmaxf(yy2 - yy1 + 1.0f, 0.0f);
            float inter = iw * ih;
            float area_o = (o.z - o.x + 1.0f) * (o.w - o.y + 1.0f);
            float iou = inter / (area_i + area_o - inter);
            if (iou > 0.5f) bits |= (1ULL << c);
        }
        g_mask[(size_t)i * MASK_W + cb] = bits;
    }
}

// ---------------------------------------------------------------------------
// Chunked greedy scan, single warp. ffs-skip over suppressed bits, 4-wide
// batched cross-chunk ORs, next-chunk diagonal prefetch. Early exit at 300.
// ---------------------------------------------------------------------------
__global__ void k_scan(float* __restrict__ out) {
    int lane = threadIdx.x;
    for (int t = lane; t < POST_NMS * 4; t += 32) out[t] = 0.0f;

    __shared__ int s_pick[POST_NMS];
    ull r0 = 0, r1 = 0, r2 = 0;
    int np = 0;
    const float inv = 1.0f / 1024.0f;

    ull f0 = g_finite[lane];
    ull f1 = g_finite[lane + 32];
    ull f2 = (lane + 64 < MASK_W) ? g_finite[lane + 64] : 0ULL;

    // preload diagonal words of chunk 0
    ull d0 = g_mask[(size_t)lane * MASK_W];
    ull d1 = g_mask[(size_t)(lane + 32) * MASK_W];

    bool stop = false;
    for (int c = 0; c < MASK_W && !stop; c++) {
        // prefetch next chunk's diagonal
        ull nd0 = 0, nd1 = 0;
        if (c + 1 < MASK_W) {
            int nb = (c + 1) * 64;
            int nrows_n = min(PRE_NMS - nb, 64);
            if (lane < nrows_n)
                nd0 = g_mask[(size_t)(nb + lane) * MASK_W + (c + 1)];
            if (lane + 32 < nrows_n)
                nd1 = g_mask[(size_t)(nb + lane + 32) * MASK_W + (c + 1)];
        }

        ull rw = (c < 32) ? r0 : ((c < 64) ? r1 : r2);
        ull r = __shfl_sync(0xffffffffu, rw, c & 31);
        ull fwv = (c < 32) ? f0 : ((c < 64) ? f1 : f2);
        ull fw = __shfl_sync(0xffffffffu, fwv, c & 31);

        int nrows = min(PRE_NMS - c * 64, 64);
        ull lim = (nrows == 64) ? ~0ULL : ((1ULL << nrows) - 1ULL);
        ull avail = ~r & lim;
        ull keptm = 0ULL;

        while (avail) {
            int b = __ffsll((long long)avail) - 1;
            keptm |= (1ULL << b);
            if ((fw >> b) & 1ULL) {
                if (lane == 0) s_pick[np] = c * 64 + b;
                np++;
                if (np == POST_NMS) { stop = true; break; }
            }
            ull dv = __shfl_sync(0xffffffffu, (b < 32) ? d0 : d1, b & 31);
            avail &= ~dv;
            avail &= ~(1ULL << b);
        }

        if (!stop) {
            ull km = keptm;
            while (km) {
                int b0 = __ffsll((long long)km) - 1; km &= km - 1;
                int b1 = -1, b2 = -1, b3 = -1;
                if (km) { b1 = __ffsll((long long)km) - 1; km &= km - 1; }
                if (km) { b2 = __ffsll((long long)km) - 1; km &= km - 1; }
                if (km) { b3 = __ffsll((long long)km) - 1; km &= km - 1; }
                const ull* p0 = &g_mask[(size_t)(c * 64 + b0) * MASK_W];
                ull a0 = p0[lane], a1 = p0[lane + 32];
                ull a2 = (lane + 64 < MASK_W) ? p0[lane + 64] : 0ULL;
                if (b1 >= 0) {
                    const ull* p = &g_mask[(size_t)(c * 64 + b1) * MASK_W];
                    a0 |= p[lane]; a1 |= p[lane + 32];
                    if (lane + 64 < MASK_W) a2 |= p[lane + 64];
                }
                if (b2 >= 0) {
                    const ull* p = &g_mask[(size_t)(c * 64 + b2) * MASK_W];
                    a0 |= p[lane]; a1 |= p[lane + 32];
                    if (lane + 64 < MASK_W) a2 |= p[lane + 64];
                }
                if (b3 >= 0) {
                    const ull* p = &g_mask[(size_t)(c * 64 + b3) * MASK_W];
                    a0 |= p[lane]; a1 |= p[lane + 32];
                    if (lane + 64 < MASK_W) a2 |= p[lane + 64];
                }
                r0 |= a0; r1 |= a1; r2 |= a2;
            }
        }
        d0 = nd0; d1 = nd1;
    }

    __syncwarp();
    for (int p = lane; p < np; p += 32) {
        int i = s_pick[p];
        float4 b = g_top[i];
        out[p * 4 + 0] = b.x * inv;
        out[p * 4 + 1] = b.y * inv;
        out[p * 4 + 2] = b.z * inv;
        out[p * 4 + 3] = b.w * inv;
    }
}

// ---------------------------------------------------------------------------
extern "C" void kernel_launch(void* const* d_in, const int* in_sizes, int n_in,
                              void* d_out, int out_size) {
    const float* scores = (const float*)d_in[0];
    const float* deltas = (const float*)d_in[1];
    float* out = (float*)d_out;

    cudaFuncSetAttribute(k_sort_final,
                         cudaFuncAttributeMaxDynamicSharedMemorySize, 65536);

    k_zero<<<9, 1024>>>();
    k_props<<<(NPROP + 1023) / 1024, 1024>>>(scores, deltas);
    k_select<<<1, 1024>>>();
    k_compact<<<(NPROP + 1023) / 1024, 1024>>>();
    k_sort_local<<<4, 1024>>>();
    k_sort_final<<<1, 1024, 65536>>>();
    k_gather<<<MASK_W, 64>>>();
    k_mask<<<dim3(MASK_W, MASK_W), 64>>>();
    k_scan<<<1, 32>>>(out);
}